// round 11
// baseline (speedup 1.0000x reference)
#include <cuda_runtime.h>
#include <cstdint>

#define Bsz 64
#define Hd 128
#define Tt 12
#define Mm 50000
#define Kk 3
#define Ee 32
#define NDd 128
#define NCc 4
#define Nn 150000          // end token id; node one-hot width = Nn+1

#define RROWS 256          // emb rows per distance block (37.5 KB smem -> 3 blocks/SM)
#define DBLK 256           // block size (1 row per thread)
#define CHUNKS ((Mm + RROWS - 1) / RROWS)   // 196
#define NBLK (Kk * CHUNKS)                  // 588 blocks
#define RSTRIDE 36         // padded smem row stride (floats); esq stored at +32

struct P {
    const float *z, *gt, *gn;
    const float *W1, *b1, *Wc, *bc, *Wh, *bh;
    const float *Wih, *bih, *Whh, *bhh;
    const float *Wt, *bt, *Wn, *bn, *Wdt, *bdt, *Wdn, *bdn, *emb;
    const int   *tids;
    float       *out;
};

// persistent per-launch state (rewritten every launch before any read)
__device__ float g_h[Bsz * Hd];
__device__ float g_c[Bsz * Hd];
__device__ __align__(16) float g_proj[Bsz * Ee];
__device__ float g_pp[Bsz];
__device__ float g_y[Bsz * NCc];
__device__ int g_tsel[Bsz];
__device__ int g_node[Tt * Bsz];      // node picks for steps 0..Tt-2 (written at t+1)
__device__ unsigned long long g_best[Bsz];

__device__ __forceinline__ float sigm(float x) { return 1.0f / (1.0f + expf(-x)); }

// monotone map float -> uint32 preserving order (finite values)
__device__ __forceinline__ unsigned ford(float f) {
    unsigned u = __float_as_uint(f);
    unsigned mask = (u & 0x80000000u) ? 0xFFFFFFFFu : 0x80000000u;
    return u ^ mask;
}

// ---------------------------------------------------------------------------
// Per-step kernel: finalize previous node pick (-> g_node), LSTM cell, type
// sample, projection. One block per batch element b, 256 threads.
// ---------------------------------------------------------------------------
__global__ void __launch_bounds__(2 * Hd) k_lstm(P p, int t) {
    const int b = blockIdx.x;
    const int tid = threadIdx.x;
    const int i = tid & (Hd - 1);
    const int grp = tid >> 7;          // 0 or 1
    const int warp = tid >> 5, lane = tid & 31;

    __shared__ __align__(16) float xs[Hd];
    __shared__ __align__(16) float s_h[Hd];
    __shared__ float s_c[Hd];
    __shared__ float gsm[2 * Hd];      // also scratch for inter at t==0
    __shared__ float projv[Ee];
    __shared__ float lg[NCc];
    __shared__ float ys[NCc];
    __shared__ int s_misc[2];          // [0]=node_id, [1]=t_idx

    if (t == 0) {
        // inter = tanh(z@W1^T + b1)
        if (tid < Hd) {
            const float* zr = p.z + (size_t)b * NDd;
            const float* w1 = p.W1 + (size_t)tid * NDd;
            float a = p.b1[tid];
#pragma unroll 4
            for (int j = 0; j < NDd; j++) a += zr[j] * w1[j];
            gsm[tid] = tanhf(a);
        }
        __syncthreads();
        // h0 = tanh(inter@Wc^T+bc) (grp0); c0 = tanh(inter@Wh^T+bh) (grp1)
        {
            const float* W  = (grp == 0) ? p.Wc : p.Wh;
            const float* bb = (grp == 0) ? p.bc : p.bh;
            float a = bb[i];
#pragma unroll 4
            for (int j = 0; j < Hd; j++) a += gsm[j] * W[(size_t)i * Hd + j];
            if (grp == 0) { s_h[i] = tanhf(a); xs[i] = 0.0f; }
            else          { s_c[i] = tanhf(a); }
        }
        __syncthreads();
    } else {
        // finalize step t-1: pick node -> g_node, build x
        if (tid < NCc) ys[tid] = g_y[b * NCc + tid];
        if (tid == 0) {
            int tprev = g_tsel[b];
            int node;
            if (tprev >= Kk) node = Nn;
            else {
                unsigned mm = ~(unsigned)(g_best[b] & 0xFFFFFFFFull);
                node = p.tids[tprev * Mm + (int)mm];
            }
            s_misc[0] = node;
            g_node[(t - 1) * Bsz + b] = node;   // one-hot written in k_final
        }
        __syncthreads();
        if (grp == 0) {
            int node = s_misc[0];
            float xv = p.bdt[i] + p.bdn[i] + p.Wdn[(size_t)i * (Nn + 1) + node];
#pragma unroll
            for (int j = 0; j < NCc; j++) xv += ys[j] * p.Wdt[i * NCc + j];
            xs[i] = xv;
            s_h[i] = g_h[b * Hd + i];
        } else {
            s_c[i] = g_c[b * Hd + i];
        }
        __syncthreads();
    }

    // gates 2-way split: grp0 -> rows i (gate i), i+2H (gate g)
    //                    grp1 -> rows i+H (gate f), i+3H (gate o)
    const int r0 = i + grp * Hd;
    const int r1 = i + (2 + grp) * Hd;
    float a0 = p.bih[r0] + p.bhh[r0];
    float a1 = p.bih[r1] + p.bhh[r1];
    {
        const float4* xi  = (const float4*)xs;
        const float4* hi  = (const float4*)s_h;
        const float4* wi0 = (const float4*)(p.Wih + (size_t)r0 * Hd);
        const float4* wi1 = (const float4*)(p.Wih + (size_t)r1 * Hd);
        const float4* wh0 = (const float4*)(p.Whh + (size_t)r0 * Hd);
        const float4* wh1 = (const float4*)(p.Whh + (size_t)r1 * Hd);
#pragma unroll 8
        for (int j = 0; j < Hd / 4; j++) {
            float4 xv = xi[j], hv = hi[j], a;
            a = wi0[j]; a0 += xv.x * a.x + xv.y * a.y + xv.z * a.z + xv.w * a.w;
            a = wh0[j]; a0 += hv.x * a.x + hv.y * a.y + hv.z * a.z + hv.w * a.w;
            a = wi1[j]; a1 += xv.x * a.x + xv.y * a.y + xv.z * a.z + xv.w * a.w;
            a = wh1[j]; a1 += hv.x * a.x + hv.y * a.y + hv.z * a.z + hv.w * a.w;
        }
    }
    if (grp == 1) { gsm[i] = a0; gsm[Hd + i] = a1; }   // stash f, o
    __syncthreads();
    if (grp == 0) {
        float cn = sigm(gsm[i]) * s_c[i] + sigm(a0) * tanhf(a1);
        float hv = sigm(gsm[Hd + i]) * tanhf(cn);
        g_c[b * Hd + i] = cn;
        g_h[b * Hd + i] = hv;
        s_h[i] = hv;
    }
    __syncthreads();

    // type logits: warps 0..3, one logit each
    if (warp < NCc) {
        const float* wt = p.Wt + warp * Hd;
        float a = 0.0f;
#pragma unroll
        for (int j = lane; j < Hd; j += 32) a += s_h[j] * wt[j];
#pragma unroll
        for (int o = 16; o; o >>= 1) a += __shfl_down_sync(0xffffffffu, a, o);
        if (lane == 0)
            lg[warp] = (a + p.bt[warp] + p.gt[((size_t)t * Bsz + b) * NCc + warp]) / 3.0f;
    }
    __syncthreads();

    if (tid == 0) {
        float v0 = lg[0], v1 = lg[1], v2 = lg[2], v3 = lg[3];
        float mx = fmaxf(fmaxf(v0, v1), fmaxf(v2, v3));
        float e0 = expf(v0 - mx), e1 = expf(v1 - mx), e2 = expf(v2 - mx), e3 = expf(v3 - mx);
        float inv = 1.0f / (e0 + e1 + e2 + e3);
        float yss[4] = { e0 * inv, e1 * inv, e2 * inv, e3 * inv };
        int am = 0; float bv = yss[0];
        if (yss[1] > bv) { bv = yss[1]; am = 1; }
        if (yss[2] > bv) { bv = yss[2]; am = 2; }
        if (yss[3] > bv) { bv = yss[3]; am = 3; }
        float yv[4] = { 0.f, 0.f, 0.f, 0.f };
        yv[am] = (1.0f - yss[am]) + yss[am];   // straight-through hard value
#pragma unroll
        for (int j = 0; j < NCc; j++) {
            g_y[b * NCc + j] = yv[j];
            p.out[((size_t)b * Tt + t) * NCc + j] = yv[j];   // type region: no memset dep
        }
        g_tsel[b] = am;
        g_best[b] = 0ull;       // reset argmax accumulator for this step
        s_misc[1] = am;
    }
    __syncthreads();

    // projection proj = h @ Wn[am]^T + bn[am] (skip when type == end);
    // 8 threads per output element
    int am = s_misc[1];
    if (am < Kk) {
        int e = tid >> 3, part = tid & 7;
        const float* wn = p.Wn + ((size_t)am * Ee + e) * Hd;
        float a = 0.0f;
#pragma unroll
        for (int jj = 0; jj < 16; jj++) { int j = part + 8 * jj; a += s_h[j] * wn[j]; }
        a += __shfl_down_sync(0xffffffffu, a, 4, 8);
        a += __shfl_down_sync(0xffffffffu, a, 2, 8);
        a += __shfl_down_sync(0xffffffffu, a, 1, 8);
        if (part == 0) {
            a += p.bn[am * Ee + e];
            g_proj[b * Ee + e] = a;
            projv[e] = a;
        }
        __syncthreads();
        if (tid < 32) {
            float v = projv[tid];
            float s2 = v * v;
#pragma unroll
            for (int o = 16; o; o >>= 1) s2 += __shfl_down_sync(0xffffffffu, s2, o);
            if (tid == 0) g_pp[b] = s2;
        }
    }
}

// ---------------------------------------------------------------------------
// Distance + gumbel-max argmax + 1/12 slice of the output-zeroing.
// Block = (k, 256-row emb chunk), 3 blocks/SM, 1 row/thread, 8 b's per pass.
// Zeroing stores are fire-and-forget and overlap the kernel's stall slack.
// z0/z1 are float4 indices into the node one-hot region (derived from the
// harness-provided out_size on the host).
// ---------------------------------------------------------------------------
__global__ void __launch_bounds__(DBLK, 3) k_dist(P p, int t, size_t z0, size_t z1) {
    extern __shared__ float sm[];
    float* embs  = sm;                               // RROWS * RSTRIDE (esq at +32)
    float* projS = embs + RROWS * RSTRIDE;           // 8 * Ee
    unsigned long long* reds = (unsigned long long*)(projS + 8 * Ee);  // 64

    __shared__ int blist[Bsz];
    __shared__ int s_gc;

    const int k = blockIdx.x / CHUNKS;
    const int chunk = blockIdx.x - k * CHUNKS;
    const int m0 = chunk * RROWS;
    const int rows = min(RROWS, Mm - m0);
    const int tid = threadIdx.x;
    const int warp = tid >> 5, lane = tid & 31;

    // ---- zero this step's slice of the node one-hot region (grid-stride) ----
    {
        float4* zbase = (float4*)(p.out + (size_t)Bsz * Tt * NCc);
        const float4 zv = make_float4(0.f, 0.f, 0.f, 0.f);
        for (size_t idx = z0 + (size_t)blockIdx.x * DBLK + tid; idx < z1;
             idx += (size_t)NBLK * DBLK)
            zbase[idx] = zv;
    }

    if (tid == 0) {
        int c = 0;
        for (int b = 0; b < Bsz; b++)
            if (g_tsel[b] == k) blist[c++] = b;
        s_gc = c;
    }

    // stage emb tile (zero-pad tail rows), conflict-free padded layout
    {
        const float4* ebase = (const float4*)(p.emb + ((size_t)k * Mm + m0) * Ee);
        int vrf4 = rows * 8;
        for (int idx = tid; idx < RROWS * 8; idx += DBLK) {
            float4 v = (idx < vrf4) ? __ldg(ebase + idx) : make_float4(0.f, 0.f, 0.f, 0.f);
            int r = idx >> 3, q = idx & 7;
            *(float4*)(embs + r * RSTRIDE + 4 * q) = v;
        }
    }
    __syncthreads();

    // per-row squared norm -> padding slot (pad rows never win)
    {
        int r = tid;
        float s = 0.0f;
#pragma unroll
        for (int q = 0; q < 8; q++) {
            float4 v = *(float4*)(embs + r * RSTRIDE + 4 * q);
            s += v.x * v.x + v.y * v.y + v.z * v.z + v.w * v.w;
        }
        embs[r * RSTRIDE + 32] = (r < rows) ? s : 1e30f;
    }
    int gc = s_gc;
    __syncthreads();
    if (gc == 0) return;

    const float* gnt = p.gn + (size_t)t * Bsz * Mm;
    const int mg = m0 + tid;
    const bool valid = (tid < rows);

    for (int p0 = 0; p0 < gc; p0 += 8) {
        int nb = min(8, gc - p0);

        // stage up to 8 projection vectors into smem
        {
            int j = tid >> 5;           // 8 x 32
            int e = tid & 31;
            float v = 0.0f;
            if (j < nb) v = g_proj[blist[p0 + j] * Ee + e];
            projS[j * Ee + e] = v;
        }

        int bj[8]; float ppj[8];
#pragma unroll
        for (int j = 0; j < 8; j++) {
            int bb = blist[p0 + (j < nb ? j : 0)];
            bj[j] = bb;
            ppj[j] = g_pp[bb];
        }

        // prefetch gumbel noise: 8 independent DRAM loads in flight per thread
        float gnv[8];
#pragma unroll
        for (int j = 0; j < 8; j++)
            gnv[j] = (j < nb && valid) ? __ldg(gnt + (size_t)bj[j] * Mm + mg) : 0.0f;
        __syncthreads();    // projS ready

        float acc[8];
#pragma unroll
        for (int j = 0; j < 8; j++) acc[j] = 0.0f;

#pragma unroll
        for (int q = 0; q < 8; q++) {
            float4 av = *(float4*)(embs + (size_t)tid * RSTRIDE + 4 * q);
#pragma unroll
            for (int j = 0; j < 8; j++) {
                float4 bv = *(float4*)(projS + j * Ee + 4 * q);
                acc[j] += av.x * bv.x + av.y * bv.y + av.z * bv.z + av.w * bv.w;
            }
        }

        float esq = embs[tid * RSTRIDE + 32];
        unsigned long long bestk[8];
#pragma unroll
        for (int j = 0; j < 8; j++) {
            unsigned long long key = 0ull;
            if (j < nb && valid) {
                float d2 = esq - 2.0f * acc[j] + ppj[j];
                float dist = sqrtf(fmaxf(d2, 0.0f));
                float sc = gnv[j] - dist;
                key = ((unsigned long long)ford(sc) << 32) | (unsigned)(~(unsigned)mg);
            }
            bestk[j] = key;
        }

        // block reduction per b, one atomicMax per (block, b)
#pragma unroll
        for (int j = 0; j < 8; j++) {
            unsigned long long kk = bestk[j];
#pragma unroll
            for (int o = 16; o; o >>= 1) {
                unsigned long long ot = __shfl_down_sync(0xffffffffu, kk, o);
                if (ot > kk) kk = ot;
            }
            if (lane == 0) reds[warp * 8 + j] = kk;
        }
        __syncthreads();
        if (tid < 8 && tid < nb) {
            int j = tid;
            unsigned long long kk = reds[j];
#pragma unroll
            for (int w2 = 1; w2 < 8; w2++) {
                unsigned long long ot = reds[w2 * 8 + j];
                if (ot > kk) kk = ot;
            }
            atomicMax(&g_best[bj[j]], kk);
        }
        __syncthreads();
    }
}

// ---------------------------------------------------------------------------
// Finalize: last step's node pick + ALL one-hot writes (node region fully
// zeroed by the 12 k_dist launches, stream-ordered before this kernel).
// ---------------------------------------------------------------------------
__global__ void k_final(P p) {
    int b = blockIdx.x;
    int tid = threadIdx.x;
    __shared__ int s_last;
    if (tid == 0) {
        int tl = g_tsel[b];
        int node;
        if (tl >= Kk) node = Nn;
        else {
            unsigned mm = ~(unsigned)(g_best[b] & 0xFFFFFFFFull);
            node = p.tids[tl * Mm + (int)mm];
        }
        s_last = node;
    }
    __syncthreads();
    if (tid < Tt) {
        int node = (tid == Tt - 1) ? s_last : g_node[tid * Bsz + b];
        p.out[(size_t)Bsz * Tt * NCc +
              ((size_t)b * Tt + tid) * (size_t)(Nn + 1) + node] = 1.0f;
    }
}

extern "C" void kernel_launch(void* const* d_in, const int* in_sizes, int n_in,
                              void* d_out, int out_size) {
    (void)in_sizes; (void)n_in;
    P p;
    p.z    = (const float*)d_in[0];
    p.gt   = (const float*)d_in[1];
    p.gn   = (const float*)d_in[2];
    p.W1   = (const float*)d_in[3];
    p.b1   = (const float*)d_in[4];
    p.Wc   = (const float*)d_in[5];
    p.bc   = (const float*)d_in[6];
    p.Wh   = (const float*)d_in[7];
    p.bh   = (const float*)d_in[8];
    p.Wih  = (const float*)d_in[9];
    p.bih  = (const float*)d_in[10];
    p.Whh  = (const float*)d_in[11];
    p.bhh  = (const float*)d_in[12];
    p.Wt   = (const float*)d_in[13];
    p.bt   = (const float*)d_in[14];
    p.Wn   = (const float*)d_in[15];
    p.bn   = (const float*)d_in[16];
    p.Wdt  = (const float*)d_in[17];
    p.bdt  = (const float*)d_in[18];
    p.Wdn  = (const float*)d_in[19];
    p.bdn  = (const float*)d_in[20];
    p.emb  = (const float*)d_in[21];
    p.tids = (const int*)d_in[22];
    p.out  = (float*)d_out;

    const int DSMEM = (RROWS * RSTRIDE + 8 * Ee) * 4 + 64 * 8;  // 38400 B
    cudaFuncSetAttribute(k_dist, cudaFuncAttributeMaxDynamicSharedMemorySize, DSMEM);

    // node one-hot region size derived from the harness's out_size
    const size_t type_elems = (size_t)Bsz * Tt * NCc;
    const size_t node_elems = (size_t)out_size - type_elems;
    const size_t ztotal4 = node_elems / 4;              // float4 count
    const size_t zstep4  = (ztotal4 + Tt - 1) / Tt;     // per-step slice

    for (int t = 0; t < Tt; t++) {
        size_t z0 = (size_t)t * zstep4;
        size_t z1 = z0 + zstep4; if (z1 > ztotal4) z1 = ztotal4;
        k_lstm<<<Bsz, 2 * Hd>>>(p, t);
        k_dist<<<NBLK, DBLK, DSMEM>>>(p, t, z0, z1);
    }
    k_final<<<Bsz, 32>>>(p);
}